// round 6
// baseline (speedup 1.0000x reference)
#include <cuda_runtime.h>
#include <cstddef>

// FCOS-style target assignment, one thread per output grid cell.
// out layout per scale: [B, S(j), S(i), 25] with channels
//   [0..19]  one-hot class map (OR over boxes covering cell)
//   [20..24] L/stride, T/stride, R/stride, B/stride, centerness
template<int S>
__global__ void assign_kernel(const float* __restrict__ bboxes,
                              const int*   __restrict__ labels,
                              float*       __restrict__ out)
{
    __shared__ float4 sbox[32];
    __shared__ int    slab[32];

    const int b = blockIdx.y;
    if (threadIdx.x < 32) {
        sbox[threadIdx.x] = reinterpret_cast<const float4*>(bboxes)[b * 32 + threadIdx.x];
        slab[threadIdx.x] = labels[b * 32 + threadIdx.x];
    }
    __syncthreads();

    const int cell = blockIdx.x * blockDim.x + threadIdx.x;
    if (cell >= S * S) return;
    const int ii = cell % S;   // x index (dim from cx)
    const int jj = cell / S;   // y index (dim from cy)

    const float stride = 416.0f / (float)S;
    const float inv_stride = (float)S / 416.0f;     // stride is 32/16/8 -> exact
    const float fii = (float)ii;
    const float fjj = (float)jj;
    const float cxc = (fii + 0.5f) * stride;        // pixel center along x
    const float cyc = (fjj + 0.5f) * stride;        // pixel center along y

    unsigned clsmask = 0u;
    float reg0 = 0.f, reg1 = 0.f, reg2 = 0.f, reg3 = 0.f, reg4 = 0.f;

    #pragma unroll 4
    for (int n = 0; n < 32; ++n) {
        const float4 bx = sbox[n];
        const float cx = bx.x, cy = bx.y, bw = bx.z, bh = bx.w;

        const float pos0 = floorf(cx * inv_stride);
        const float pos1 = floorf(cy * inv_stride);
        const float bp0  = floorf(0.5f * bw * inv_stride);
        const float bp1  = floorf(0.5f * bh * inv_stride);

        const bool ri = (fii >= pos0 - bp0) && (fii < pos0 + bp0);
        const bool rj = (fjj >= pos1 - bp1) && (fjj < pos1 + bp1);
        const bool region = ri && rj;

        if (region) clsmask |= (1u << slab[n]);

        const float hw = floorf(bw * 0.5f);
        const float hh = floorf(bh * 0.5f);
        const float l  = cxc - (cx - hw);
        const float r  = (cx + hw) - cxc;
        const float t  = cyc - (cy - hh);
        const float bo = (cy + hh) - cyc;

        const float mlr = fmaxf(l, r);
        const float mtb = fmaxf(t, bo);
        const float m   = fmaxf(mlr, mtb);

        bool band;
        if (S == 13)      band = (m > 256.0f);
        else if (S == 26) band = (m > 64.0f) && (m <= 256.0f);
        else              band = (m <= 64.0f);

        if (region && band) {
            const float regmax = fmaxf(fmaxf(fmaxf(reg0, reg1), fmaxf(reg2, reg3)), reg4);
            if (regmax == 0.0f || m < regmax) {
                const float cent = sqrtf(fminf(l, r) * fminf(t, bo) / (mlr * mtb));
                reg0 = fmaxf(l  * inv_stride, 0.0f);
                reg1 = fmaxf(t  * inv_stride, 0.0f);
                reg2 = fmaxf(r  * inv_stride, 0.0f);
                reg3 = fmaxf(bo * inv_stride, 0.0f);
                reg4 = fmaxf(cent, 0.0f);
            }
        }
    }

    float* o = out + ((size_t)(b * S + jj) * S + ii) * 25;
    #pragma unroll
    for (int c = 0; c < 20; ++c)
        o[c] = ((clsmask >> c) & 1u) ? 1.0f : 0.0f;
    o[20] = reg0; o[21] = reg1; o[22] = reg2; o[23] = reg3; o[24] = reg4;
}

extern "C" void kernel_launch(void* const* d_in, const int* in_sizes, int n_in,
                              void* d_out, int out_size)
{
    const float* image  = (const float*)d_in[0];
    const float* bboxes = (const float*)d_in[1];
    const int*   labels = (const int*)  d_in[2];
    float* out = (float*)d_out;

    const size_t n_img = (size_t)in_sizes[0];            // 64*3*416*416
    constexpr int B = 64;
    constexpr size_t T13 = (size_t)B * 13 * 13 * 25;
    constexpr size_t T26 = (size_t)B * 26 * 26 * 25;

    // Image passthrough: bulk D2D copy (graph-capturable).
    cudaMemcpyAsync(out, image, n_img * sizeof(float), cudaMemcpyDeviceToDevice);

    float* o13 = out + n_img;
    float* o26 = o13 + T13;
    float* o52 = o26 + T26;

    assign_kernel<13><<<dim3(1,  B), 256>>>(bboxes, labels, o13);
    assign_kernel<26><<<dim3(3,  B), 256>>>(bboxes, labels, o26);
    assign_kernel<52><<<dim3(11, B), 256>>>(bboxes, labels, o52);
}

// round 7
// speedup vs baseline: 1.0043x; 1.0043x over previous
#include <cuda_runtime.h>
#include <cstddef>

// FCOS-style target assignment, one thread per output grid cell.
// out layout per scale: [B, S(j), S(i), 25] with channels
//   [0..19]  one-hot class map (OR over boxes covering cell)
//   [20..24] L/stride, T/stride, R/stride, B/stride, centerness
template<int S>
__global__ void assign_kernel(const float* __restrict__ bboxes,
                              const int*   __restrict__ labels,
                              float*       __restrict__ out)
{
    __shared__ float4 sbox[32];
    __shared__ int    slab[32];

    const int b = blockIdx.y;
    if (threadIdx.x < 32) {
        sbox[threadIdx.x] = reinterpret_cast<const float4*>(bboxes)[b * 32 + threadIdx.x];
        slab[threadIdx.x] = labels[b * 32 + threadIdx.x];
    }
    __syncthreads();

    const int cell = blockIdx.x * blockDim.x + threadIdx.x;
    if (cell >= S * S) return;
    const int ii = cell % S;   // x index (dim from cx)
    const int jj = cell / S;   // y index (dim from cy)

    const float stride = 416.0f / (float)S;
    const float inv_stride = (float)S / 416.0f;     // stride is 32/16/8 -> exact
    const float fii = (float)ii;
    const float fjj = (float)jj;
    const float cxc = (fii + 0.5f) * stride;        // pixel center along x
    const float cyc = (fjj + 0.5f) * stride;        // pixel center along y

    unsigned clsmask = 0u;
    float reg0 = 0.f, reg1 = 0.f, reg2 = 0.f, reg3 = 0.f, reg4 = 0.f;

    #pragma unroll 4
    for (int n = 0; n < 32; ++n) {
        const float4 bx = sbox[n];
        const float cx = bx.x, cy = bx.y, bw = bx.z, bh = bx.w;

        const float pos0 = floorf(cx * inv_stride);
        const float pos1 = floorf(cy * inv_stride);
        const float bp0  = floorf(0.5f * bw * inv_stride);
        const float bp1  = floorf(0.5f * bh * inv_stride);

        const bool ri = (fii >= pos0 - bp0) && (fii < pos0 + bp0);
        const bool rj = (fjj >= pos1 - bp1) && (fjj < pos1 + bp1);
        const bool region = ri && rj;

        if (region) clsmask |= (1u << slab[n]);

        const float hw = floorf(bw * 0.5f);
        const float hh = floorf(bh * 0.5f);
        const float l  = cxc - (cx - hw);
        const float r  = (cx + hw) - cxc;
        const float t  = cyc - (cy - hh);
        const float bo = (cy + hh) - cyc;

        const float mlr = fmaxf(l, r);
        const float mtb = fmaxf(t, bo);
        const float m   = fmaxf(mlr, mtb);

        bool band;
        if (S == 13)      band = (m > 256.0f);
        else if (S == 26) band = (m > 64.0f) && (m <= 256.0f);
        else              band = (m <= 64.0f);

        if (region && band) {
            const float regmax = fmaxf(fmaxf(fmaxf(reg0, reg1), fmaxf(reg2, reg3)), reg4);
            if (regmax == 0.0f || m < regmax) {
                const float cent = sqrtf(fminf(l, r) * fminf(t, bo) / (mlr * mtb));
                reg0 = fmaxf(l  * inv_stride, 0.0f);
                reg1 = fmaxf(t  * inv_stride, 0.0f);
                reg2 = fmaxf(r  * inv_stride, 0.0f);
                reg3 = fmaxf(bo * inv_stride, 0.0f);
                reg4 = fmaxf(cent, 0.0f);
            }
        }
    }

    float* o = out + ((size_t)(b * S + jj) * S + ii) * 25;
    #pragma unroll
    for (int c = 0; c < 20; ++c)
        o[c] = ((clsmask >> c) & 1u) ? 1.0f : 0.0f;
    o[20] = reg0; o[21] = reg1; o[22] = reg2; o[23] = reg3; o[24] = reg4;
}

extern "C" void kernel_launch(void* const* d_in, const int* in_sizes, int n_in,
                              void* d_out, int out_size)
{
    const float* image  = (const float*)d_in[0];
    const float* bboxes = (const float*)d_in[1];
    const int*   labels = (const int*)  d_in[2];
    float* out = (float*)d_out;

    const size_t n_img = (size_t)in_sizes[0];            // 64*3*416*416
    constexpr int B = 64;
    constexpr size_t T13 = (size_t)B * 13 * 13 * 25;
    constexpr size_t T26 = (size_t)B * 26 * 26 * 25;

    // Image passthrough: bulk D2D copy (graph-capturable).
    cudaMemcpyAsync(out, image, n_img * sizeof(float), cudaMemcpyDeviceToDevice);

    float* o13 = out + n_img;
    float* o26 = o13 + T13;
    float* o52 = o26 + T26;

    assign_kernel<13><<<dim3(1,  B), 256>>>(bboxes, labels, o13);
    assign_kernel<26><<<dim3(3,  B), 256>>>(bboxes, labels, o26);
    assign_kernel<52><<<dim3(11, B), 256>>>(bboxes, labels, o52);
}